// round 6
// baseline (speedup 1.0000x reference)
#include <cuda_runtime.h>
#include <cstdint>
#include <cstddef>

#define BATCH 256
#define SEQT  365
#define HID   256
#define INSZ  32
#define G4    1024          // 4*HID
#define NB    128           // persistent blocks
#define NT    512           // threads per block (256 batch x 2 k-halves)
#define NTX   256           // xw_kernel threads
#define NPAIR (HID / 2)     // 128 unit pairs

typedef unsigned long long ull;

// ---------------- scratch (static device allocations; no cudaMalloc) ----------
// xw packed per unit-pair: [t][pair][2][b] float4
//   slot 0 = (f0,f1,i0,i1), slot 1 = (o0,o1,g0,g1), bias folded in. 382 MB.
__device__ float4 g_xw4[(size_t)SEQT * NPAIR * 2 * BATCH];
// hidden state, double buffered, packed 4 units per float4: [buf][k4][b]
__device__ float4 g_h4[2][(HID / 4) * BATCH];
__device__ unsigned g_bar_count;
__device__ unsigned g_bar_gen;

// ---------------- packed f32x2 helpers (PTX-only; ptxas won't auto-fuse) ------
__device__ __forceinline__ ull pack2(float lo, float hi) {
    ull r;
    asm("mov.b64 %0, {%1, %2};" : "=l"(r) : "f"(lo), "f"(hi));
    return r;
}
__device__ __forceinline__ void unpack2(ull v, float& lo, float& hi) {
    asm("mov.b64 {%0, %1}, %2;" : "=f"(lo), "=f"(hi) : "l"(v));
}
__device__ __forceinline__ ull fma2(ull a, ull b, ull c) {
    ull d;
    asm("fma.rn.f32x2 %0, %1, %2, %3;" : "=l"(d) : "l"(a), "l"(b), "l"(c));
    return d;
}
__device__ __forceinline__ ull add2(ull a, ull b) {
    ull d;
    asm("add.rn.f32x2 %0, %1, %2;" : "=l"(d) : "l"(a), "l"(b));
    return d;
}
__device__ __forceinline__ float sigf(float x) { return 1.0f / (1.0f + __expf(-x)); }

// ---------------- grid barrier (all NB CTAs co-resident by construction) ------
__device__ __forceinline__ void grid_barrier() {
    __syncthreads();
    if (threadIdx.x == 0) {
        volatile unsigned* genp = &g_bar_gen;
        unsigned gen = *genp;
        __threadfence();                       // make h writes L2-visible
        if (atomicAdd(&g_bar_count, 1u) == NB - 1u) {
            g_bar_count = 0;
            __threadfence();
            *genp = gen + 1u;                  // release
        } else {
            while (*genp == gen) { }           // spin in L2
        }
    }
    __syncthreads();
}

// ============================================================================
// Kernel A: xw. grid (SEQT, 8); block = one t, a 32-unit tile (16 pairs).
// Output layout matches lstm reader: g_xw4[t][pair][slot][b].
// ============================================================================
__global__ void __launch_bounds__(NTX) xw_kernel(const float* __restrict__ x,
                                                 const float* __restrict__ w_ih,
                                                 const float* __restrict__ bias) {
    __shared__ float ws[INSZ][16][8];     // [k][pair_local][c]
    const int t   = blockIdx.x;
    const int u00 = blockIdx.y * 32;
    const int tid = threadIdx.x;

    for (int i = tid; i < INSZ * 128; i += NTX) {
        int k = i >> 7, r = i & 127, p = r >> 3, c = r & 7;
        int unit = u00 + 2 * p + (c & 1);
        ws[k][p][c] = w_ih[(size_t)k * G4 + (c >> 1) * HID + unit];
    }
    __syncthreads();

    const int b = tid;
    ull xk2[INSZ];
    const float4* xp = (const float4*)(x + ((size_t)b * SEQT + t) * INSZ);
#pragma unroll
    for (int q = 0; q < INSZ / 4; q++) {
        float4 v = xp[q];
        xk2[4 * q + 0] = pack2(v.x, v.x);
        xk2[4 * q + 1] = pack2(v.y, v.y);
        xk2[4 * q + 2] = pack2(v.z, v.z);
        xk2[4 * q + 3] = pack2(v.w, v.w);
    }

    for (int p = 0; p < 16; p++) {
        int u = u00 + 2 * p;
        ull aF = pack2(bias[u],           bias[u + 1]);
        ull aI = pack2(bias[HID + u],     bias[HID + u + 1]);
        ull aO = pack2(bias[2 * HID + u], bias[2 * HID + u + 1]);
        ull aG = pack2(bias[3 * HID + u], bias[3 * HID + u + 1]);
#pragma unroll
        for (int k = 0; k < INSZ; k++) {
            ulonglong2 wA = *(const ulonglong2*)(&ws[k][p][0]);
            ulonglong2 wB = *(const ulonglong2*)(&ws[k][p][4]);
            aF = fma2(xk2[k], wA.x, aF);
            aI = fma2(xk2[k], wA.y, aI);
            aO = fma2(xk2[k], wB.x, aO);
            aG = fma2(xk2[k], wB.y, aG);
        }
        float f0, f1, i0, i1, o0, o1, g0, g1;
        unpack2(aF, f0, f1); unpack2(aI, i0, i1);
        unpack2(aO, o0, o1); unpack2(aG, g0, g1);
        size_t base = (((size_t)t * NPAIR + (u00 / 2 + p)) * 2) * BATCH + b;
        __stcs(&g_xw4[base],         make_float4(f0, f1, i0, i1));
        __stcs(&g_xw4[base + BATCH], make_float4(o0, o1, g0, g1));
    }
}

// ============================================================================
// Kernel B: persistent recurrent LSTM, split-k x2.
// CTA owns units u0=2*bid, u0+1. Thread (kh, b): kh = tid>>8 picks k-half,
// b = tid&255 is the batch row. 16 warps/CTA -> 4 warps/SMSP for latency hiding.
// kh=1 partials are combined into kh=0 via SMEM; kh=0 does activations + stores.
// ============================================================================
__global__ void __launch_bounds__(NT, 1) lstm_kernel(const float* __restrict__ w_hh,
                                                     const float* __restrict__ fc_w,
                                                     const float* __restrict__ fc_b,
                                                     float* __restrict__ out) {
    __shared__ float ws[HID][8];          // [k][c], 8 KB
    __shared__ ulonglong2 redA[BATCH];    // (aF, aI) from kh=1, 4 KB
    __shared__ ulonglong2 redB[BATCH];    // (aO, aG) from kh=1, 4 KB
    __shared__ float redf[NT];

    const int bid = blockIdx.x;
    const int tid = threadIdx.x;
    const int u0  = bid * 2;
    const int b   = tid & 255;
    const int kh  = tid >> 8;             // constant per warp

    for (int i = tid; i < HID * 8; i += NT) {
        int k = i >> 3, c = i & 7;
        ws[k][c] = w_hh[(size_t)k * G4 + (c >> 1) * HID + u0 + (c & 1)];
    }
    __syncthreads();

    float c0 = 0.0f, c1 = 0.0f;

    float* outO = out;
    float* outH = out + BATCH;
    float* outC = outH + (size_t)BATCH * SEQT * HID;

    // xw prefetch for t = 0 (kh=0 threads only)
    const size_t xw_stride_t = (size_t)NPAIR * 2 * BATCH;
    const float4* xwp = g_xw4 + (size_t)bid * 2 * BATCH + b;
    float4 xA = make_float4(0, 0, 0, 0), xB = xA;
    if (kh == 0) { xA = __ldcs(xwp); xB = __ldcs(xwp + BATCH); }

    const int kb4 = kh * 32;              // this half's first float4-k index

    for (int t = 0; t < SEQT; t++) {
        ull aF, aI, aO, aG;
        if (kh == 0) {
            aF = pack2(xA.x, xA.y);
            aI = pack2(xA.z, xA.w);
            aO = pack2(xB.x, xB.y);
            aG = pack2(xB.z, xB.w);
            if (t + 1 < SEQT) {
                const float4* nx = xwp + (size_t)(t + 1) * xw_stride_t;
                xA = __ldcs(nx);
                xB = __ldcs(nx + BATCH);
            }
        } else {
            aF = 0; aI = 0; aO = 0; aG = 0;
        }

        if (t > 0) {
            const float4* hp = (const float4*)g_h4[t & 1] + b;
            float4 hb[2][4];
#pragma unroll
            for (int i = 0; i < 4; i++)
                hb[0][i] = __ldcg(hp + (kb4 + i) * BATCH);
#pragma unroll
            for (int c = 0; c < 8; c++) {           // 8 chunks x 16 k = 128 k
                if (c < 7) {
#pragma unroll
                    for (int i = 0; i < 4; i++)
                        hb[(c + 1) & 1][i] = __ldcg(hp + (kb4 + (c + 1) * 4 + i) * BATCH);
                }
#pragma unroll
                for (int i = 0; i < 4; i++) {
                    float4 v = hb[c & 1][i];
                    const float* wr = &ws[(kb4 + c * 4 + i) * 4][0];
#pragma unroll
                    for (int s = 0; s < 4; s++) {
                        float hv = (s == 0) ? v.x : (s == 1) ? v.y : (s == 2) ? v.z : v.w;
                        ull h2 = pack2(hv, hv);
                        ulonglong2 wA = *(const ulonglong2*)(wr + 8 * s);
                        ulonglong2 wB = *(const ulonglong2*)(wr + 8 * s + 4);
                        aF = fma2(h2, wA.x, aF);
                        aI = fma2(h2, wA.y, aI);
                        aO = fma2(h2, wB.x, aO);
                        aG = fma2(h2, wB.y, aG);
                    }
                }
            }
        }

        // ---- combine the two k-halves ----
        if (kh == 1) {
            redA[b] = make_ulonglong2(aF, aI);
            redB[b] = make_ulonglong2(aO, aG);
        }
        __syncthreads();

        if (kh == 0) {
            ulonglong2 rA = redA[b];
            ulonglong2 rB = redB[b];
            aF = add2(aF, rA.x);
            aI = add2(aI, rA.y);
            aO = add2(aO, rB.x);
            aG = add2(aG, rB.y);

            float f0, f1, i0, i1, o0, o1, gg0, gg1;
            unpack2(aF, f0, f1); unpack2(aI, i0, i1);
            unpack2(aO, o0, o1); unpack2(aG, gg0, gg1);

            c0 = sigf(f0) * c0 + sigf(i0) * tanhf(gg0);
            c1 = sigf(f1) * c1 + sigf(i1) * tanhf(gg1);
            float h0 = sigf(o0) * tanhf(c0);
            float h1 = sigf(o1) * tanhf(c1);

            // packed h for next step: g_h4[(t+1)&1][u0>>2][b], comps (u0&3, +1)
            {
                float* hw = (float*)&g_h4[(t + 1) & 1][(u0 >> 2) * BATCH + b];
                *(float2*)(hw + (u0 & 3)) = make_float2(h0, h1);
            }

            size_t ob = ((size_t)b * SEQT + t) * HID + u0;
            __stcs((float2*)(outH + ob), make_float2(h0, h1));
            __stcs((float2*)(outC + ob), make_float2(c0, c1));
        }

        grid_barrier();
    }

    // ---- final FC: out[bo] = h_last[bo,:] . fc_w + fc_b ----
    const float* hl = (const float*)g_h4[SEQT & 1];
    float fw = (tid < 256) ? fc_w[tid] : 0.0f;
    float fb = fc_b[0];
    for (int bb = 0; bb < 2; bb++) {
        int bo = bid * 2 + bb;
        float v = 0.0f;
        if (tid < 256)
            v = __ldcg(hl + ((tid >> 2) * BATCH + bo) * 4 + (tid & 3)) * fw;
        redf[tid] = v;
        __syncthreads();
        for (int s = NT / 2; s > 0; s >>= 1) {
            if (tid < s) redf[tid] += redf[tid + s];
            __syncthreads();
        }
        if (tid == 0) outO[bo] = redf[0] + fb;
        __syncthreads();
    }
}

// ============================================================================
extern "C" void kernel_launch(void* const* d_in, const int* in_sizes, int n_in,
                              void* d_out, int out_size) {
    const float* x    = (const float*)d_in[0];  // (256, 365, 32)
    const float* w_ih = (const float*)d_in[1];  // (32, 1024)
    const float* w_hh = (const float*)d_in[2];  // (256, 1024)
    const float* bias = (const float*)d_in[3];  // (1024,)
    const float* fc_w = (const float*)d_in[4];  // (256, 1)
    const float* fc_b = (const float*)d_in[5];  // (1,)
    float* out = (float*)d_out;

    dim3 gA(SEQT, 8);
    xw_kernel<<<gA, NTX>>>(x, w_ih, bias);
    lstm_kernel<<<NB, NT>>>(w_hh, fc_w, fc_b, out);
}

// round 7
// speedup vs baseline: 1.2592x; 1.2592x over previous
#include <cuda_runtime.h>
#include <cstdint>
#include <cstddef>

#define BATCH 256
#define SEQT  365
#define HID   256
#define INSZ  32
#define G4    1024          // 4*HID
#define NB    128           // persistent blocks
#define NT    256           // lstm threads: 8 warps = 2 b-halves x 4 k-quarters
#define NTX   256           // xw_kernel threads
#define NPAIR (HID / 2)     // 128 unit pairs

typedef unsigned long long ull;

// ---------------- scratch (static device allocations; no cudaMalloc) ----------
// xw packed per unit-pair: [t][pair][2][b] float4
//   slot 0 = (f0,f1,i0,i1), slot 1 = (o0,o1,g0,g1), bias folded in. 382 MB.
__device__ float4 g_xw4[(size_t)SEQT * NPAIR * 2 * BATCH];
// hidden state, double buffered, [buf][k][b] floats (b contiguous)
__device__ float g_hb[2][HID * BATCH];
__device__ unsigned g_bar_count;
__device__ unsigned g_bar_gen;

// ---------------- packed f32x2 helpers (PTX-only; ptxas won't auto-fuse) ------
__device__ __forceinline__ ull pack2(float lo, float hi) {
    ull r;
    asm("mov.b64 %0, {%1, %2};" : "=l"(r) : "f"(lo), "f"(hi));
    return r;
}
__device__ __forceinline__ void unpack2(ull v, float& lo, float& hi) {
    asm("mov.b64 {%0, %1}, %2;" : "=f"(lo), "=f"(hi) : "l"(v));
}
__device__ __forceinline__ ull fma2(ull a, ull b, ull c) {
    ull d;
    asm("fma.rn.f32x2 %0, %1, %2, %3;" : "=l"(d) : "l"(a), "l"(b), "l"(c));
    return d;
}
__device__ __forceinline__ ull add2(ull a, ull b) {
    ull d;
    asm("add.rn.f32x2 %0, %1, %2;" : "=l"(d) : "l"(a), "l"(b));
    return d;
}
__device__ __forceinline__ float sigf(float x) { return 1.0f / (1.0f + __expf(-x)); }

__device__ __forceinline__ unsigned swz(unsigned off) {   // SW128-style bank spread
    return off ^ ((off >> 3) & 0x70);
}

// ---------------- grid barrier (all NB CTAs co-resident by construction) ------
__device__ __forceinline__ void grid_barrier() {
    __syncthreads();
    if (threadIdx.x == 0) {
        volatile unsigned* genp = &g_bar_gen;
        unsigned gen = *genp;
        __threadfence();                       // make h writes L2-visible
        if (atomicAdd(&g_bar_count, 1u) == NB - 1u) {
            g_bar_count = 0;
            __threadfence();
            *genp = gen + 1u;                  // release
        } else {
            while (*genp == gen) { }           // spin in L2
        }
    }
    __syncthreads();
}

// ============================================================================
// Kernel A: xw. grid (SEQT, 8); block = one t, a 32-unit tile (16 pairs).
// Output layout matches lstm reader: g_xw4[t][pair][slot][b].
// ============================================================================
__global__ void __launch_bounds__(NTX) xw_kernel(const float* __restrict__ x,
                                                 const float* __restrict__ w_ih,
                                                 const float* __restrict__ bias) {
    __shared__ float ws[INSZ][16][8];     // [k][pair_local][c]
    const int t   = blockIdx.x;
    const int u00 = blockIdx.y * 32;
    const int tid = threadIdx.x;

    for (int i = tid; i < INSZ * 128; i += NTX) {
        int k = i >> 7, r = i & 127, p = r >> 3, c = r & 7;
        int unit = u00 + 2 * p + (c & 1);
        ws[k][p][c] = w_ih[(size_t)k * G4 + (c >> 1) * HID + unit];
    }
    __syncthreads();

    const int b = tid;
    ull xk2[INSZ];
    const float4* xp = (const float4*)(x + ((size_t)b * SEQT + t) * INSZ);
#pragma unroll
    for (int q = 0; q < INSZ / 4; q++) {
        float4 v = xp[q];
        xk2[4 * q + 0] = pack2(v.x, v.x);
        xk2[4 * q + 1] = pack2(v.y, v.y);
        xk2[4 * q + 2] = pack2(v.z, v.z);
        xk2[4 * q + 3] = pack2(v.w, v.w);
    }

    for (int p = 0; p < 16; p++) {
        int u = u00 + 2 * p;
        ull aF = pack2(bias[u],           bias[u + 1]);
        ull aI = pack2(bias[HID + u],     bias[HID + u + 1]);
        ull aO = pack2(bias[2 * HID + u], bias[2 * HID + u + 1]);
        ull aG = pack2(bias[3 * HID + u], bias[3 * HID + u + 1]);
#pragma unroll
        for (int k = 0; k < INSZ; k++) {
            ulonglong2 wA = *(const ulonglong2*)(&ws[k][p][0]);
            ulonglong2 wB = *(const ulonglong2*)(&ws[k][p][4]);
            aF = fma2(xk2[k], wA.x, aF);
            aI = fma2(xk2[k], wA.y, aI);
            aO = fma2(xk2[k], wB.x, aO);
            aG = fma2(xk2[k], wB.y, aG);
        }
        float f0, f1, i0, i1, o0, o1, g0, g1;
        unpack2(aF, f0, f1); unpack2(aI, i0, i1);
        unpack2(aO, o0, o1); unpack2(aG, g0, g1);
        size_t base = (((size_t)t * NPAIR + (u00 / 2 + p)) * 2) * BATCH + b;
        __stcs(&g_xw4[base],         make_float4(f0, f1, i0, i1));
        __stcs(&g_xw4[base + BATCH], make_float4(o0, o1, g0, g1));
    }
}

// ============================================================================
// Kernel B: persistent recurrent LSTM, batch-register-tiled.
// CTA owns units u0=2*bid, u0+1 (8 gate cols = 4 f32x2 pairs).
// Warp w: bh = w&1 (b-half of 128), kh = w>>1 (k-quarter of 64).
// Lane l:  bg = l>>1 (8-batch group), cg = l&1 (pair group: {f,i} or {o,g}).
// Lane tile = 8 b x 2 pairs: per k ONE broadcast LDS.128 feeds 16 fma2.
// Partials reduced over kh via swizzled SMEM; activation phase: thread = b.
// ============================================================================
__global__ void __launch_bounds__(NT, 1) lstm_kernel(const float* __restrict__ w_hh,
                                                     const float* __restrict__ fc_w,
                                                     const float* __restrict__ fc_b,
                                                     float* __restrict__ out) {
    __shared__ float ws[HID][8];            // [k][c], c = pair*2 + half, 8 KB
    __shared__ ull sm_part[4 * BATCH * 4];  // [kh][b][pair] swizzled, 32 KB
    __shared__ float redf[NT];

    const int bid = blockIdx.x;
    const int tid = threadIdx.x;
    const int u0  = bid * 2;
    const int w   = tid >> 5;
    const int l   = tid & 31;
    const int bh  = w & 1;
    const int kh  = w >> 1;              // 0..3
    const int bg  = l >> 1;              // 0..15
    const int cg  = l & 1;               // 0..1
    const int b0  = bh * 128 + bg * 8;   // lane's first batch
    const int kb  = kh * 64;             // lane's first k
    const int b   = tid;                 // activation-phase batch

    for (int i = tid; i < HID * 8; i += NT) {
        int k = i >> 3, c = i & 7;
        ws[k][c] = w_hh[(size_t)k * G4 + (c >> 1) * HID + u0 + (c & 1)];
    }
    __syncthreads();

    float cc0 = 0.0f, cc1 = 0.0f;

    float* outO = out;
    float* outH = out + BATCH;
    float* outC = outH + (size_t)BATCH * SEQT * HID;

    // xw prefetch for t = 0 (every thread, b = tid)
    const size_t xw_stride_t = (size_t)NPAIR * 2 * BATCH;
    const float4* xwp = g_xw4 + (size_t)bid * 2 * BATCH + b;
    float4 xA = __ldcs(xwp);
    float4 xB = __ldcs(xwp + BATCH);

    const int hoff4 = bh * 32 + bg * 2;  // float4 offset of lane's 8 batches

    for (int t = 0; t < SEQT; t++) {
        ull acc[8][2];
#pragma unroll
        for (int bb = 0; bb < 8; bb++) { acc[bb][0] = 0; acc[bb][1] = 0; }

        if (t > 0) {
            const float4* hp4 = (const float4*)g_hb[t & 1] + hoff4;
            float4 hA[2][4], hB[2][4];
#pragma unroll
            for (int j = 0; j < 4; j++) {
                hA[0][j] = __ldcg(hp4 + (size_t)(kb + j) * 64);
                hB[0][j] = __ldcg(hp4 + (size_t)(kb + j) * 64 + 1);
            }
#pragma unroll
            for (int ch = 0; ch < 16; ch++) {        // 16 chunks x 4 k = 64 k
                const int cur = ch & 1, nxt = cur ^ 1;
                if (ch < 15) {
#pragma unroll
                    for (int j = 0; j < 4; j++) {
                        hA[nxt][j] = __ldcg(hp4 + (size_t)(kb + (ch + 1) * 4 + j) * 64);
                        hB[nxt][j] = __ldcg(hp4 + (size_t)(kb + (ch + 1) * 4 + j) * 64 + 1);
                    }
                }
#pragma unroll
                for (int j = 0; j < 4; j++) {
                    const int k = kb + ch * 4 + j;
                    ulonglong2 wv = *(const ulonglong2*)(&ws[k][cg * 4]);
                    float4 va = hA[cur][j], vb = hB[cur][j];
                    ull h2;
                    h2 = pack2(va.x, va.x);
                    acc[0][0] = fma2(h2, wv.x, acc[0][0]);
                    acc[0][1] = fma2(h2, wv.y, acc[0][1]);
                    h2 = pack2(va.y, va.y);
                    acc[1][0] = fma2(h2, wv.x, acc[1][0]);
                    acc[1][1] = fma2(h2, wv.y, acc[1][1]);
                    h2 = pack2(va.z, va.z);
                    acc[2][0] = fma2(h2, wv.x, acc[2][0]);
                    acc[2][1] = fma2(h2, wv.y, acc[2][1]);
                    h2 = pack2(va.w, va.w);
                    acc[3][0] = fma2(h2, wv.x, acc[3][0]);
                    acc[3][1] = fma2(h2, wv.y, acc[3][1]);
                    h2 = pack2(vb.x, vb.x);
                    acc[4][0] = fma2(h2, wv.x, acc[4][0]);
                    acc[4][1] = fma2(h2, wv.y, acc[4][1]);
                    h2 = pack2(vb.y, vb.y);
                    acc[5][0] = fma2(h2, wv.x, acc[5][0]);
                    acc[5][1] = fma2(h2, wv.y, acc[5][1]);
                    h2 = pack2(vb.z, vb.z);
                    acc[6][0] = fma2(h2, wv.x, acc[6][0]);
                    acc[6][1] = fma2(h2, wv.y, acc[6][1]);
                    h2 = pack2(vb.w, vb.w);
                    acc[7][0] = fma2(h2, wv.x, acc[7][0]);
                    acc[7][1] = fma2(h2, wv.y, acc[7][1]);
                }
            }
        }

        // ---- store partials (swizzled) ----
#pragma unroll
        for (int bb = 0; bb < 8; bb++) {
            unsigned off = (unsigned)(((kh * 256 + b0 + bb) * 4 + cg * 2) * 8);
            *(ulonglong2*)((char*)sm_part + swz(off)) =
                make_ulonglong2(acc[bb][0], acc[bb][1]);
        }
        __syncthreads();

        // ---- activation phase: thread = batch b ----
        ull aF = pack2(xA.x, xA.y);
        ull aI = pack2(xA.z, xA.w);
        ull aO = pack2(xB.x, xB.y);
        ull aG = pack2(xB.z, xB.w);
        if (t + 1 < SEQT) {
            const float4* nx = xwp + (size_t)(t + 1) * xw_stride_t;
            xA = __ldcs(nx);
            xB = __ldcs(nx + BATCH);
        }
#pragma unroll
        for (int q = 0; q < 4; q++) {
            unsigned off = (unsigned)(((q * 256 + b) * 4) * 8);
            ulonglong2 v0 = *(const ulonglong2*)((const char*)sm_part + swz(off));
            ulonglong2 v1 = *(const ulonglong2*)((const char*)sm_part + swz(off + 16));
            aF = add2(aF, v0.x);
            aI = add2(aI, v0.y);
            aO = add2(aO, v1.x);
            aG = add2(aG, v1.y);
        }

        float f0, f1, i0, i1, o0, o1, gg0, gg1;
        unpack2(aF, f0, f1); unpack2(aI, i0, i1);
        unpack2(aO, o0, o1); unpack2(aG, gg0, gg1);

        cc0 = sigf(f0) * cc0 + sigf(i0) * tanhf(gg0);
        cc1 = sigf(f1) * cc1 + sigf(i1) * tanhf(gg1);
        float h0 = sigf(o0) * tanhf(cc0);
        float h1 = sigf(o1) * tanhf(cc1);

        float* hw = g_hb[(t + 1) & 1];
        hw[u0 * BATCH + b]       = h0;      // coalesced over b
        hw[(u0 + 1) * BATCH + b] = h1;

        size_t ob = ((size_t)b * SEQT + t) * HID + u0;
        __stcs((float2*)(outH + ob), make_float2(h0, h1));
        __stcs((float2*)(outC + ob), make_float2(cc0, cc1));

        grid_barrier();
    }

    // ---- final FC: out[bo] = h_last[bo,:] . fc_w + fc_b ----
    const float* hl = g_hb[SEQT & 1];
    float fw = fc_w[tid];
    float fb = fc_b[0];
    for (int bb = 0; bb < 2; bb++) {
        int bo = u0 + bb;
        redf[tid] = __ldcg(hl + tid * BATCH + bo) * fw;   // k = tid
        __syncthreads();
        for (int s = NT / 2; s > 0; s >>= 1) {
            if (tid < s) redf[tid] += redf[tid + s];
            __syncthreads();
        }
        if (tid == 0) outO[bo] = redf[0] + fb;
        __syncthreads();
    }
}

// ============================================================================
extern "C" void kernel_launch(void* const* d_in, const int* in_sizes, int n_in,
                              void* d_out, int out_size) {
    const float* x    = (const float*)d_in[0];  // (256, 365, 32)
    const float* w_ih = (const float*)d_in[1];  // (32, 1024)
    const float* w_hh = (const float*)d_in[2];  // (256, 1024)
    const float* bias = (const float*)d_in[3];  // (1024,)
    const float* fc_w = (const float*)d_in[4];  // (256, 1)
    const float* fc_b = (const float*)d_in[5];  // (1,)
    float* out = (float*)d_out;

    dim3 gA(SEQT, 8);
    xw_kernel<<<gA, NTX>>>(x, w_ih, bias);
    lstm_kernel<<<NB, NT>>>(w_hh, fc_w, fc_b, out);
}